// round 12
// baseline (speedup 1.0000x reference)
#include <cuda_runtime.h>
#include <cuda_fp16.h>
#include <cstdint>

#define BB   4
#define SS   2048
#define DD   1024
#define HH   16
#define DKK  64
#define GM   (BB*SS)
#define GK   DD
#define GN   DD

// ---------------------------------------------------------------------------
// Scratch (device globals; allocation-free per harness rules)
// ---------------------------------------------------------------------------
__device__ float gQ[BB*SS*DD];
__device__ float gK[BB*SS*DD];
__device__ float gV[BB*SS*DD];
__device__ float gC[BB*SS*DD];

// ---------------------------------------------------------------------------
// Helpers
// ---------------------------------------------------------------------------
__device__ __forceinline__ unsigned f2tf(float f) {
    unsigned r;
    asm("cvt.rna.tf32.f32 %0, %1;" : "=r"(r) : "f"(f));
    return r;
}
__device__ __forceinline__ float ex2(float x) {
    float r;
    asm("ex2.approx.ftz.f32 %0, %1;" : "=f"(r) : "f"(x));
    return r;
}
__device__ __forceinline__ unsigned packh2(float lo, float hi) {
    __half2 h = __floats2half2_rn(lo, hi);   // .x (low 16 bits) = lo
    return *(unsigned*)&h;
}
__device__ __forceinline__ void mma_tf32(float& d0, float& d1, float& d2, float& d3,
                                         unsigned a0, unsigned a1, unsigned a2, unsigned a3,
                                         unsigned b0, unsigned b1) {
    asm("mma.sync.aligned.m16n8k8.row.col.f32.tf32.tf32.f32 "
        "{%0,%1,%2,%3},{%4,%5,%6,%7},{%8,%9},{%0,%1,%2,%3};"
        : "+f"(d0), "+f"(d1), "+f"(d2), "+f"(d3)
        : "r"(a0), "r"(a1), "r"(a2), "r"(a3), "r"(b0), "r"(b1));
}
__device__ __forceinline__ void mma_f16(float& d0, float& d1, float& d2, float& d3,
                                        unsigned a0, unsigned a1, unsigned a2, unsigned a3,
                                        unsigned b0, unsigned b1) {
    asm("mma.sync.aligned.m16n8k16.row.col.f32.f16.f16.f32 "
        "{%0,%1,%2,%3},{%4,%5,%6,%7},{%8,%9},{%0,%1,%2,%3};"
        : "+f"(d0), "+f"(d1), "+f"(d2), "+f"(d3)
        : "r"(a0), "r"(a1), "r"(a2), "r"(a3), "r"(b0), "r"(b1));
}

// ---------------------------------------------------------------------------
// GEMM v5 (fp16 m16n8k16): C = fp16(X) @ fp16(W) + bias.
// = round-11 v4 with the A-staging mapping FIXED for coalescing:
// 8 lanes per row (contiguous 128B LDG.128), pack adjacent-k half2, STS.64.
// CTA 128x128x32, 128 thr / 4 warps (2m x 2n), warp tile 64x64.
// ---------------------------------------------------------------------------
#define ASTRH 20
#define BSTRH 136

__global__ __launch_bounds__(128)
void gemm_bias(const float* __restrict__ X, const float* __restrict__ W,
               const float* __restrict__ bias, float* __restrict__ C, int round_out) {
    __shared__ unsigned Ah[128 * ASTRH];   // 10 KB
    __shared__ unsigned Bh[16 * BSTRH];    // 8.5 KB

    const int tid  = threadIdx.x;
    const int wid  = tid >> 5;
    const int lane = tid & 31;
    const int g    = lane >> 2;
    const int t    = lane & 3;
    const int wm   = wid & 1;
    const int wn   = wid >> 1;
    const int m0   = blockIdx.y * 128;
    const int n0   = blockIdx.x * 128;

    float acc[4][8][4];
#pragma unroll
    for (int mf = 0; mf < 4; mf++)
#pragma unroll
        for (int nf = 0; nf < 8; nf++)
#pragma unroll
            for (int r = 0; r < 4; r++) acc[mf][nf][r] = 0.f;

    for (int kt = 0; kt < GK / 32; kt++) {
        __syncthreads();
        // A staging (FIXED): idx -> (r = idx>>3, cc = idx&7); 8 lanes cover a
        // row's 128B contiguously. Pack (c,c+1) half2 pairs -> STS.64.
#pragma unroll
        for (int i = 0; i < 8; i++) {
            int idx = tid + i * 128;
            int r = idx >> 3, cc = idx & 7;
            float4 v = *(const float4*)(X + (size_t)(m0 + r) * GK + kt * 32 + 4 * cc);
            uint2 o;
            o.x = packh2(v.x, v.y);
            o.y = packh2(v.z, v.w);
            *(uint2*)&Ah[r * ASTRH + 2 * cc] = o;
        }
        // B staging: pair-rows (proven coalesced). idx -> (pr = idx>>5, c = idx&31)
#pragma unroll
        for (int i = 0; i < 4; i++) {
            int idx = tid + i * 128;
            int pr = idx >> 5, c = idx & 31;
            const float* gp = W + (size_t)(kt * 32 + 2 * pr) * GN + n0 + 4 * c;
            float4 wa = *(const float4*)gp;
            float4 wb = *(const float4*)(gp + GN);
            uint4 o;
            o.x = packh2(wa.x, wb.x);
            o.y = packh2(wa.y, wb.y);
            o.z = packh2(wa.z, wb.z);
            o.w = packh2(wa.w, wb.w);
            *(uint4*)&Bh[pr * BSTRH + 4 * c] = o;
        }
        __syncthreads();

#pragma unroll
        for (int ks = 0; ks < 2; ks++) {
            unsigned a[4][4];
#pragma unroll
            for (int mf = 0; mf < 4; mf++) {
                int rb = wm * 64 + mf * 16;
                a[mf][0] = Ah[(rb + g)     * ASTRH + ks * 8 + t];
                a[mf][1] = Ah[(rb + g + 8) * ASTRH + ks * 8 + t];
                a[mf][2] = Ah[(rb + g)     * ASTRH + ks * 8 + t + 4];
                a[mf][3] = Ah[(rb + g + 8) * ASTRH + ks * 8 + t + 4];
            }
#pragma unroll
            for (int nf = 0; nf < 8; nf++) {
                unsigned b0 = Bh[(ks * 8 + t)     * BSTRH + wn * 64 + nf * 8 + g];
                unsigned b1 = Bh[(ks * 8 + t + 4) * BSTRH + wn * 64 + nf * 8 + g];
#pragma unroll
                for (int mf = 0; mf < 4; mf++)
                    mma_f16(acc[mf][nf][0], acc[mf][nf][1], acc[mf][nf][2], acc[mf][nf][3],
                            a[mf][0], a[mf][1], a[mf][2], a[mf][3], b0, b1);
            }
        }
    }

#pragma unroll
    for (int mf = 0; mf < 4; mf++) {
#pragma unroll
        for (int nf = 0; nf < 8; nf++) {
            int row = m0 + wm * 64 + mf * 16 + g;
            int col = n0 + wn * 64 + nf * 8 + 2 * t;
            float bv0 = bias[col], bv1 = bias[col + 1];
            float v00 = acc[mf][nf][0] + bv0;
            float v01 = acc[mf][nf][1] + bv1;
            float v10 = acc[mf][nf][2] + bv0;
            float v11 = acc[mf][nf][3] + bv1;
            if (round_out) {
                v00 = __uint_as_float(f2tf(v00));
                v01 = __uint_as_float(f2tf(v01));
                v10 = __uint_as_float(f2tf(v10));
                v11 = __uint_as_float(f2tf(v11));
            }
            C[(size_t)row * GN + col]           = v00;
            C[(size_t)row * GN + col + 1]       = v01;
            C[(size_t)(row + 8) * GN + col]     = v10;
            C[(size_t)(row + 8) * GN + col + 1] = v11;
        }
    }
}

// ---------------------------------------------------------------------------
// Flash attention v6 (PROVEN 474.6us, verbatim):
// QK^T tf32 (K permuted stride 68), P*V fp16 m16n8k16 (V half2 row-pairs).
// ---------------------------------------------------------------------------
#define KST 68
#define VST2 72
#define VOFF (128*KST)
#define ATTN_SMEM ((128*KST + 64*VST2) * 4)   // 53248 bytes

__global__ __launch_bounds__(256)
void attn_kernel(const float* __restrict__ gq, const float* __restrict__ gk,
                 const float* __restrict__ gv, float* __restrict__ gc) {
    extern __shared__ unsigned sm[];
    unsigned* Ks = sm;              // k-permuted tf32 [128][KST]
    unsigned* Vp = sm + VOFF;       // half2 row-pairs [64][VST2]

    const int b  = blockIdx.z;
    const int h  = blockIdx.y;
    const int q0 = blockIdx.x * 128;
    const int tid  = threadIdx.x;
    const int wid  = tid >> 5;
    const int lane = tid & 31;
    const int g    = lane >> 2;
    const int t    = lane & 3;
    const float L2E = 1.44269504f;

    unsigned qf[8][4];
    {
        const float* Qb = gq + ((size_t)(b * SS + q0 + wid * 16)) * DD + h * DKK;
#pragma unroll
        for (int ks = 0; ks < 8; ks++) {
            qf[ks][0] = __float_as_uint(Qb[(size_t)g * DD + ks * 8 + t] * 0.125f);
            qf[ks][1] = __float_as_uint(Qb[(size_t)(g + 8) * DD + ks * 8 + t] * 0.125f);
            qf[ks][2] = __float_as_uint(Qb[(size_t)g * DD + ks * 8 + t + 4] * 0.125f);
            qf[ks][3] = __float_as_uint(Qb[(size_t)(g + 8) * DD + ks * 8 + t + 4] * 0.125f);
        }
    }

    float mr0 = -1e30f, mr1 = -1e30f, l0 = 0.f, l1 = 0.f;
    float oacc[8][4];
#pragma unroll
    for (int nf = 0; nf < 8; nf++)
#pragma unroll
        for (int r = 0; r < 4; r++) oacc[nf][r] = 0.f;

    const uint4* Kb = (const uint4*)(gk + (size_t)b * SS * DD + h * DKK);
    const float* Vb = gv + (size_t)b * SS * DD + h * DKK;
    const int RSTR4 = DD / 4;

    for (int kt = 0; kt < SS / 128; kt++) {
        __syncthreads();
#pragma unroll
        for (int i = 0; i < 8; i++) {
            int idx = tid + i * 256;
            int r = idx >> 4, c4 = idx & 15, c = c4 * 4;
            uint4 kv = Kb[(size_t)(kt * 128 + r) * RSTR4 + c4];
            int kbase = r * KST;
            Ks[kbase + ((c + 0) & 7) * 8 + ((c + 0) >> 3)] = kv.x;
            Ks[kbase + ((c + 1) & 7) * 8 + ((c + 1) >> 3)] = kv.y;
            Ks[kbase + ((c + 2) & 7) * 8 + ((c + 2) >> 3)] = kv.z;
            Ks[kbase + ((c + 3) & 7) * 8 + ((c + 3) >> 3)] = kv.w;
        }
#pragma unroll
        for (int i = 0; i < 4; i++) {
            int idx = tid + i * 256;
            int rp = idx >> 4, c4 = idx & 15;
            const float* g0 = Vb + (size_t)(kt * 128 + 2 * rp) * DD + c4 * 4;
            float4 va = *(const float4*)g0;
            float4 vb2 = *(const float4*)(g0 + DD);
            uint4 o;
            o.x = packh2(va.x, vb2.x);
            o.y = packh2(va.y, vb2.y);
            o.z = packh2(va.z, vb2.z);
            o.w = packh2(va.w, vb2.w);
            *(uint4*)&Vp[rp * VST2 + c4 * 4] = o;
        }
        __syncthreads();

        float sacc[16][4];
#pragma unroll
        for (int nf = 0; nf < 16; nf++)
#pragma unroll
            for (int r = 0; r < 4; r++) sacc[nf][r] = 0.f;

#pragma unroll
        for (int nf = 0; nf < 16; nf++) {
            const uint4* kp = (const uint4*)&Ks[(nf * 8 + g) * KST + t * 8];
            uint4 k0 = kp[0], k1 = kp[1];
            const uint4* kq = (const uint4*)&Ks[(nf * 8 + g) * KST + (t + 4) * 8];
            uint4 k2 = kq[0], k3 = kq[1];
            mma_tf32(sacc[nf][0], sacc[nf][1], sacc[nf][2], sacc[nf][3],
                     qf[0][0], qf[0][1], qf[0][2], qf[0][3], k0.x, k2.x);
            mma_tf32(sacc[nf][0], sacc[nf][1], sacc[nf][2], sacc[nf][3],
                     qf[1][0], qf[1][1], qf[1][2], qf[1][3], k0.y, k2.y);
            mma_tf32(sacc[nf][0], sacc[nf][1], sacc[nf][2], sacc[nf][3],
                     qf[2][0], qf[2][1], qf[2][2], qf[2][3], k0.z, k2.z);
            mma_tf32(sacc[nf][0], sacc[nf][1], sacc[nf][2], sacc[nf][3],
                     qf[3][0], qf[3][1], qf[3][2], qf[3][3], k0.w, k2.w);
            mma_tf32(sacc[nf][0], sacc[nf][1], sacc[nf][2], sacc[nf][3],
                     qf[4][0], qf[4][1], qf[4][2], qf[4][3], k1.x, k3.x);
            mma_tf32(sacc[nf][0], sacc[nf][1], sacc[nf][2], sacc[nf][3],
                     qf[5][0], qf[5][1], qf[5][2], qf[5][3], k1.y, k3.y);
            mma_tf32(sacc[nf][0], sacc[nf][1], sacc[nf][2], sacc[nf][3],
                     qf[6][0], qf[6][1], qf[6][2], qf[6][3], k1.z, k3.z);
            mma_tf32(sacc[nf][0], sacc[nf][1], sacc[nf][2], sacc[nf][3],
                     qf[7][0], qf[7][1], qf[7][2], qf[7][3], k1.w, k3.w);
        }

        float rmax0 = -1e30f, rmax1 = -1e30f;
#pragma unroll
        for (int nf = 0; nf < 16; nf++) {
            rmax0 = fmaxf(rmax0, fmaxf(sacc[nf][0], sacc[nf][1]));
            rmax1 = fmaxf(rmax1, fmaxf(sacc[nf][2], sacc[nf][3]));
        }
        rmax0 = fmaxf(rmax0, __shfl_xor_sync(0xffffffffu, rmax0, 1));
        rmax0 = fmaxf(rmax0, __shfl_xor_sync(0xffffffffu, rmax0, 2));
        rmax1 = fmaxf(rmax1, __shfl_xor_sync(0xffffffffu, rmax1, 1));
        rmax1 = fmaxf(rmax1, __shfl_xor_sync(0xffffffffu, rmax1, 2));
        float mn0 = fmaxf(mr0, rmax0), mn1 = fmaxf(mr1, rmax1);
        float alpha0 = ex2((mr0 - mn0) * L2E);
        float alpha1 = ex2((mr1 - mn1) * L2E);
        mr0 = mn0; mr1 = mn1;

        unsigned pah[16][2];
        float rs0 = 0.f, rs1 = 0.f;
#pragma unroll
        for (int nf = 0; nf < 16; nf++) {
            float p0 = ex2((sacc[nf][0] - mn0) * L2E);
            float p1 = ex2((sacc[nf][1] - mn0) * L2E);
            float p2 = ex2((sacc[nf][2] - mn1) * L2E);
            float p3 = ex2((sacc[nf][3] - mn1) * L2E);
            rs0 += p0 + p1;
            rs1 += p2 + p3;
            pah[nf][0] = packh2(p0, p1);
            pah[nf][1] = packh2(p2, p3);
        }
        rs0 += __shfl_xor_sync(0xffffffffu, rs0, 1);
        rs0 += __shfl_xor_sync(0xffffffffu, rs0, 2);
        rs1 += __shfl_xor_sync(0xffffffffu, rs1, 1);
        rs1 += __shfl_xor_sync(0xffffffffu, rs1, 2);
        l0 = l0 * alpha0 + rs0;
        l1 = l1 * alpha1 + rs1;
#pragma unroll
        for (int nf = 0; nf < 8; nf++) {
            oacc[nf][0] *= alpha0; oacc[nf][1] *= alpha0;
            oacc[nf][2] *= alpha1; oacc[nf][3] *= alpha1;
        }

#pragma unroll
        for (int nf = 0; nf < 8; nf++) {
#pragma unroll
            for (int kp = 0; kp < 8; kp++) {
                unsigned b0 = Vp[(kp * 8 + t)     * VST2 + nf * 8 + g];
                unsigned b1 = Vp[(kp * 8 + t + 4) * VST2 + nf * 8 + g];
                mma_f16(oacc[nf][0], oacc[nf][1], oacc[nf][2], oacc[nf][3],
                        pah[2 * kp][0], pah[2 * kp][1],
                        pah[2 * kp + 1][0], pah[2 * kp + 1][1], b0, b1);
            }
        }
    }

    float inv0 = 1.f / l0, inv1 = 1.f / l1;
    float* Cb = gc + ((size_t)(b * SS + q0 + wid * 16)) * DD + h * DKK;
#pragma unroll
    for (int nf = 0; nf < 8; nf++) {
        int c = nf * 8 + 2 * t;
        Cb[(size_t)g * DD + c]           = __uint_as_float(f2tf(oacc[nf][0] * inv0));
        Cb[(size_t)g * DD + c + 1]       = __uint_as_float(f2tf(oacc[nf][1] * inv0));
        Cb[(size_t)(g + 8) * DD + c]     = __uint_as_float(f2tf(oacc[nf][2] * inv1));
        Cb[(size_t)(g + 8) * DD + c + 1] = __uint_as_float(f2tf(oacc[nf][3] * inv1));
    }
}

// ---------------------------------------------------------------------------
// Launch: 5 separate kernels.
// ---------------------------------------------------------------------------
extern "C" void kernel_launch(void* const* d_in, const int* in_sizes, int n_in,
                              void* d_out, int out_size) {
    const float* query = (const float*)d_in[0];
    const float* key_  = (const float*)d_in[1];
    const float* value = (const float*)d_in[2];
    const float* Wq = (const float*)d_in[3];
    const float* bq = (const float*)d_in[4];
    const float* Wk = (const float*)d_in[5];
    const float* bk = (const float*)d_in[6];
    const float* Wv = (const float*)d_in[7];
    const float* bv = (const float*)d_in[8];
    const float* Wo = (const float*)d_in[9];
    const float* bo = (const float*)d_in[10];
    float* out = (float*)d_out;

    float *pQ, *pK, *pV, *pC;
    cudaGetSymbolAddress((void**)&pQ, gQ);
    cudaGetSymbolAddress((void**)&pK, gK);
    cudaGetSymbolAddress((void**)&pV, gV);
    cudaGetSymbolAddress((void**)&pC, gC);

    cudaFuncSetAttribute(attn_kernel, cudaFuncAttributeMaxDynamicSharedMemorySize, ATTN_SMEM);

    dim3 ggrid(GN / 128, GM / 128);   // (8, 64)
    gemm_bias<<<ggrid, 128>>>(query, Wq, bq, pQ, 1);
    gemm_bias<<<ggrid, 128>>>(key_,  Wk, bk, pK, 1);
    gemm_bias<<<ggrid, 128>>>(value, Wv, bv, pV, 1);

    attn_kernel<<<dim3(SS / 128, HH, BB), 256, ATTN_SMEM>>>(pQ, pK, pV, pC);

    gemm_bias<<<ggrid, 128>>>(pC, Wo, bo, out, 0);
}

// round 13
// speedup vs baseline: 1.2040x; 1.2040x over previous
#include <cuda_runtime.h>
#include <cuda_fp16.h>
#include <cstdint>

#define BB   4
#define SS   2048
#define DD   1024
#define HH   16
#define DKK  64
#define GM   (BB*SS)
#define GK   DD
#define GN   DD

// ---------------------------------------------------------------------------
// Scratch (device globals; allocation-free per harness rules)
// ---------------------------------------------------------------------------
__device__ float gQ[BB*SS*DD];
__device__ float gK[BB*SS*DD];
__device__ float gV[BB*SS*DD];
__device__ float gC[BB*SS*DD];

// ---------------------------------------------------------------------------
// Helpers
// ---------------------------------------------------------------------------
__device__ __forceinline__ unsigned f2tf(float f) {
    unsigned r;
    asm("cvt.rna.tf32.f32 %0, %1;" : "=r"(r) : "f"(f));
    return r;
}
__device__ __forceinline__ float ex2(float x) {
    float r;
    asm("ex2.approx.ftz.f32 %0, %1;" : "=f"(r) : "f"(x));
    return r;
}
__device__ __forceinline__ unsigned packh2(float lo, float hi) {
    __half2 h = __floats2half2_rn(lo, hi);   // .x (low 16 bits) = lo
    return *(unsigned*)&h;
}
__device__ __forceinline__ void mma_tf32(float& d0, float& d1, float& d2, float& d3,
                                         unsigned a0, unsigned a1, unsigned a2, unsigned a3,
                                         unsigned b0, unsigned b1) {
    asm("mma.sync.aligned.m16n8k8.row.col.f32.tf32.tf32.f32 "
        "{%0,%1,%2,%3},{%4,%5,%6,%7},{%8,%9},{%0,%1,%2,%3};"
        : "+f"(d0), "+f"(d1), "+f"(d2), "+f"(d3)
        : "r"(a0), "r"(a1), "r"(a2), "r"(a3), "r"(b0), "r"(b1));
}
__device__ __forceinline__ void mma_f16(float& d0, float& d1, float& d2, float& d3,
                                        unsigned a0, unsigned a1, unsigned a2, unsigned a3,
                                        unsigned b0, unsigned b1) {
    asm("mma.sync.aligned.m16n8k16.row.col.f32.f16.f16.f32 "
        "{%0,%1,%2,%3},{%4,%5,%6,%7},{%8,%9},{%0,%1,%2,%3};"
        : "+f"(d0), "+f"(d1), "+f"(d2), "+f"(d3)
        : "r"(a0), "r"(a1), "r"(a2), "r"(a3), "r"(b0), "r"(b1));
}

// ---------------------------------------------------------------------------
// GEMM v3 (PROVEN ~135us, byte-exact round 9/10): tf32 m16n8k8.
// CTA 128x128x32, 128 thr / 4 warps (2m x 2n), warp tile 64x64.
// ---------------------------------------------------------------------------
#define ASTR 36
#define BSTR 132

__global__ __launch_bounds__(128)
void gemm_bias(const float* __restrict__ X, const float* __restrict__ W,
               const float* __restrict__ bias, float* __restrict__ C, int round_out) {
    __shared__ unsigned As[128 * ASTR];
    __shared__ unsigned Bs[32 * BSTR];

    const int tid  = threadIdx.x;
    const int wid  = tid >> 5;
    const int lane = tid & 31;
    const int g    = lane >> 2;
    const int t    = lane & 3;
    const int wm   = wid & 1;
    const int wn   = wid >> 1;
    const int m0   = blockIdx.y * 128;
    const int n0   = blockIdx.x * 128;

    float acc[4][8][4];
#pragma unroll
    for (int mf = 0; mf < 4; mf++)
#pragma unroll
        for (int nf = 0; nf < 8; nf++)
#pragma unroll
            for (int r = 0; r < 4; r++) acc[mf][nf][r] = 0.f;

    for (int kt = 0; kt < GK / 32; kt++) {
        __syncthreads();
#pragma unroll
        for (int i = 0; i < 8; i++) {
            int idx = tid + i * 128;
            int r = idx >> 3, c4 = idx & 7;
            float4 v = *(const float4*)(X + (size_t)(m0 + r) * GK + kt * 32 + c4 * 4);
            unsigned* dst = &As[r * ASTR + c4 * 4];
            dst[0] = f2tf(v.x); dst[1] = f2tf(v.y); dst[2] = f2tf(v.z); dst[3] = f2tf(v.w);
        }
#pragma unroll
        for (int i = 0; i < 8; i++) {
            int idx = tid + i * 128;
            int r = idx >> 5, c4 = idx & 31;
            float4 v = *(const float4*)(W + (size_t)(kt * 32 + r) * GN + n0 + c4 * 4);
            unsigned* dst = &Bs[r * BSTR + c4 * 4];
            dst[0] = f2tf(v.x); dst[1] = f2tf(v.y); dst[2] = f2tf(v.z); dst[3] = f2tf(v.w);
        }
        __syncthreads();

#pragma unroll
        for (int ks = 0; ks < 4; ks++) {
            unsigned a[4][4];
#pragma unroll
            for (int mf = 0; mf < 4; mf++) {
                int rb = wm * 64 + mf * 16;
                a[mf][0] = As[(rb + g)     * ASTR + ks * 8 + t];
                a[mf][1] = As[(rb + g + 8) * ASTR + ks * 8 + t];
                a[mf][2] = As[(rb + g)     * ASTR + ks * 8 + t + 4];
                a[mf][3] = As[(rb + g + 8) * ASTR + ks * 8 + t + 4];
            }
#pragma unroll
            for (int nf = 0; nf < 8; nf++) {
                unsigned b0 = Bs[(ks * 8 + t)     * BSTR + wn * 64 + nf * 8 + g];
                unsigned b1 = Bs[(ks * 8 + t + 4) * BSTR + wn * 64 + nf * 8 + g];
#pragma unroll
                for (int mf = 0; mf < 4; mf++)
                    mma_tf32(acc[mf][nf][0], acc[mf][nf][1], acc[mf][nf][2], acc[mf][nf][3],
                             a[mf][0], a[mf][1], a[mf][2], a[mf][3], b0, b1);
            }
        }
    }

#pragma unroll
    for (int mf = 0; mf < 4; mf++) {
#pragma unroll
        for (int nf = 0; nf < 8; nf++) {
            int row = m0 + wm * 64 + mf * 16 + g;
            int col = n0 + wn * 64 + nf * 8 + 2 * t;
            float bv0 = bias[col], bv1 = bias[col + 1];
            float v00 = acc[mf][nf][0] + bv0;
            float v01 = acc[mf][nf][1] + bv1;
            float v10 = acc[mf][nf][2] + bv0;
            float v11 = acc[mf][nf][3] + bv1;
            if (round_out) {
                v00 = __uint_as_float(f2tf(v00));
                v01 = __uint_as_float(f2tf(v01));
                v10 = __uint_as_float(f2tf(v10));
                v11 = __uint_as_float(f2tf(v11));
            }
            C[(size_t)row * GN + col]           = v00;
            C[(size_t)row * GN + col + 1]       = v01;
            C[(size_t)(row + 8) * GN + col]     = v10;
            C[(size_t)(row + 8) * GN + col + 1] = v11;
        }
    }
}

// ---------------------------------------------------------------------------
// Flash attention v7: round-10 v6 math verbatim, but CTA split for occupancy:
// q-tile 64, 128 threads / 4 warps, 2 CTAs/SM (regs 184*128=23.5K, smem 53KB).
// Two CTAs per SM overlap: one stages K/V + softmax while the other runs mmas.
// ---------------------------------------------------------------------------
#define KST 68
#define VST2 72
#define VOFF (128*KST)
#define ATTN_SMEM ((128*KST + 64*VST2) * 4)   // 53248 bytes

__global__ __launch_bounds__(128)
void attn_kernel(const float* __restrict__ gq, const float* __restrict__ gk,
                 const float* __restrict__ gv, float* __restrict__ gc) {
    extern __shared__ unsigned sm[];
    unsigned* Ks = sm;              // k-permuted tf32 [128][KST]
    unsigned* Vp = sm + VOFF;       // half2 row-pairs [64][VST2]

    const int b  = blockIdx.z;
    const int h  = blockIdx.y;
    const int q0 = blockIdx.x * 64;
    const int tid  = threadIdx.x;
    const int wid  = tid >> 5;      // 0..3
    const int lane = tid & 31;
    const int g    = lane >> 2;
    const int t    = lane & 3;
    const float L2E = 1.44269504f;

    // Q fragments: warp wid owns q rows [q0 + wid*16, +16)
    unsigned qf[8][4];
    {
        const float* Qb = gq + ((size_t)(b * SS + q0 + wid * 16)) * DD + h * DKK;
#pragma unroll
        for (int ks = 0; ks < 8; ks++) {
            qf[ks][0] = __float_as_uint(Qb[(size_t)g * DD + ks * 8 + t] * 0.125f);
            qf[ks][1] = __float_as_uint(Qb[(size_t)(g + 8) * DD + ks * 8 + t] * 0.125f);
            qf[ks][2] = __float_as_uint(Qb[(size_t)g * DD + ks * 8 + t + 4] * 0.125f);
            qf[ks][3] = __float_as_uint(Qb[(size_t)(g + 8) * DD + ks * 8 + t + 4] * 0.125f);
        }
    }

    float mr0 = -1e30f, mr1 = -1e30f, l0 = 0.f, l1 = 0.f;
    float oacc[8][4];
#pragma unroll
    for (int nf = 0; nf < 8; nf++)
#pragma unroll
        for (int r = 0; r < 4; r++) oacc[nf][r] = 0.f;

    const uint4* Kb = (const uint4*)(gk + (size_t)b * SS * DD + h * DKK);
    const float* Vb = gv + (size_t)b * SS * DD + h * DKK;
    const int RSTR4 = DD / 4;

    for (int kt = 0; kt < SS / 128; kt++) {
        __syncthreads();
        // K staging: 2048 uint4 / 128 thr = 16 each (same (r,c4) map as proven)
#pragma unroll
        for (int i = 0; i < 16; i++) {
            int idx = tid + i * 128;
            int r = idx >> 4, c4 = idx & 15, c = c4 * 4;
            uint4 kv = Kb[(size_t)(kt * 128 + r) * RSTR4 + c4];
            int kbase = r * KST;
            Ks[kbase + ((c + 0) & 7) * 8 + ((c + 0) >> 3)] = kv.x;
            Ks[kbase + ((c + 1) & 7) * 8 + ((c + 1) >> 3)] = kv.y;
            Ks[kbase + ((c + 2) & 7) * 8 + ((c + 2) >> 3)] = kv.z;
            Ks[kbase + ((c + 3) & 7) * 8 + ((c + 3) >> 3)] = kv.w;
        }
        // V staging: 1024 / 128 thr = 8 each
#pragma unroll
        for (int i = 0; i < 8; i++) {
            int idx = tid + i * 128;
            int rp = idx >> 4, c4 = idx & 15;
            const float* g0 = Vb + (size_t)(kt * 128 + 2 * rp) * DD + c4 * 4;
            float4 va = *(const float4*)g0;
            float4 vb2 = *(const float4*)(g0 + DD);
            uint4 o;
            o.x = packh2(va.x, vb2.x);
            o.y = packh2(va.y, vb2.y);
            o.z = packh2(va.z, vb2.z);
            o.w = packh2(va.w, vb2.w);
            *(uint4*)&Vp[rp * VST2 + c4 * 4] = o;
        }
        __syncthreads();

        // S = Q K^T : 16 x 128 per warp (tf32)
        float sacc[16][4];
#pragma unroll
        for (int nf = 0; nf < 16; nf++)
#pragma unroll
            for (int r = 0; r < 4; r++) sacc[nf][r] = 0.f;

#pragma unroll
        for (int nf = 0; nf < 16; nf++) {
            const uint4* kp = (const uint4*)&Ks[(nf * 8 + g) * KST + t * 8];
            uint4 k0 = kp[0], k1 = kp[1];
            const uint4* kq = (const uint4*)&Ks[(nf * 8 + g) * KST + (t + 4) * 8];
            uint4 k2 = kq[0], k3 = kq[1];
            mma_tf32(sacc[nf][0], sacc[nf][1], sacc[nf][2], sacc[nf][3],
                     qf[0][0], qf[0][1], qf[0][2], qf[0][3], k0.x, k2.x);
            mma_tf32(sacc[nf][0], sacc[nf][1], sacc[nf][2], sacc[nf][3],
                     qf[1][0], qf[1][1], qf[1][2], qf[1][3], k0.y, k2.y);
            mma_tf32(sacc[nf][0], sacc[nf][1], sacc[nf][2], sacc[nf][3],
                     qf[2][0], qf[2][1], qf[2][2], qf[2][3], k0.z, k2.z);
            mma_tf32(sacc[nf][0], sacc[nf][1], sacc[nf][2], sacc[nf][3],
                     qf[3][0], qf[3][1], qf[3][2], qf[3][3], k0.w, k2.w);
            mma_tf32(sacc[nf][0], sacc[nf][1], sacc[nf][2], sacc[nf][3],
                     qf[4][0], qf[4][1], qf[4][2], qf[4][3], k1.x, k3.x);
            mma_tf32(sacc[nf][0], sacc[nf][1], sacc[nf][2], sacc[nf][3],
                     qf[5][0], qf[5][1], qf[5][2], qf[5][3], k1.y, k3.y);
            mma_tf32(sacc[nf][0], sacc[nf][1], sacc[nf][2], sacc[nf][3],
                     qf[6][0], qf[6][1], qf[6][2], qf[6][3], k1.z, k3.z);
            mma_tf32(sacc[nf][0], sacc[nf][1], sacc[nf][2], sacc[nf][3],
                     qf[7][0], qf[7][1], qf[7][2], qf[7][3], k1.w, k3.w);
        }

        // online softmax
        float rmax0 = -1e30f, rmax1 = -1e30f;
#pragma unroll
        for (int nf = 0; nf < 16; nf++) {
            rmax0 = fmaxf(rmax0, fmaxf(sacc[nf][0], sacc[nf][1]));
            rmax1 = fmaxf(rmax1, fmaxf(sacc[nf][2], sacc[nf][3]));
        }
        rmax0 = fmaxf(rmax0, __shfl_xor_sync(0xffffffffu, rmax0, 1));
        rmax0 = fmaxf(rmax0, __shfl_xor_sync(0xffffffffu, rmax0, 2));
        rmax1 = fmaxf(rmax1, __shfl_xor_sync(0xffffffffu, rmax1, 1));
        rmax1 = fmaxf(rmax1, __shfl_xor_sync(0xffffffffu, rmax1, 2));
        float mn0 = fmaxf(mr0, rmax0), mn1 = fmaxf(mr1, rmax1);
        float alpha0 = ex2((mr0 - mn0) * L2E);
        float alpha1 = ex2((mr1 - mn1) * L2E);
        mr0 = mn0; mr1 = mn1;

        // exp + fp16 pack (accumulator layout == fp16 A-fragment layout)
        unsigned pah[16][2];
        float rs0 = 0.f, rs1 = 0.f;
#pragma unroll
        for (int nf = 0; nf < 16; nf++) {
            float p0 = ex2((sacc[nf][0] - mn0) * L2E);
            float p1 = ex2((sacc[nf][1] - mn0) * L2E);
            float p2 = ex2((sacc[nf][2] - mn1) * L2E);
            float p3 = ex2((sacc[nf][3] - mn1) * L2E);
            rs0 += p0 + p1;
            rs1 += p2 + p3;
            pah[nf][0] = packh2(p0, p1);
            pah[nf][1] = packh2(p2, p3);
        }
        rs0 += __shfl_xor_sync(0xffffffffu, rs0, 1);
        rs0 += __shfl_xor_sync(0xffffffffu, rs0, 2);
        rs1 += __shfl_xor_sync(0xffffffffu, rs1, 1);
        rs1 += __shfl_xor_sync(0xffffffffu, rs1, 2);
        l0 = l0 * alpha0 + rs0;
        l1 = l1 * alpha1 + rs1;
#pragma unroll
        for (int nf = 0; nf < 8; nf++) {
            oacc[nf][0] *= alpha0; oacc[nf][1] *= alpha0;
            oacc[nf][2] *= alpha1; oacc[nf][3] *= alpha1;
        }

        // O += P V : fp16 m16n8k16
#pragma unroll
        for (int nf = 0; nf < 8; nf++) {
#pragma unroll
            for (int kp = 0; kp < 8; kp++) {
                unsigned b0 = Vp[(kp * 8 + t)     * VST2 + nf * 8 + g];
                unsigned b1 = Vp[(kp * 8 + t + 4) * VST2 + nf * 8 + g];
                mma_f16(oacc[nf][0], oacc[nf][1], oacc[nf][2], oacc[nf][3],
                        pah[2 * kp][0], pah[2 * kp][1],
                        pah[2 * kp + 1][0], pah[2 * kp + 1][1], b0, b1);
            }
        }
    }

    // epilogue: normalize + round (ctx feeds the tf32 O-projection)
    float inv0 = 1.f / l0, inv1 = 1.f / l1;
    float* Cb = gc + ((size_t)(b * SS + q0 + wid * 16)) * DD + h * DKK;
#pragma unroll
    for (int nf = 0; nf < 8; nf++) {
        int c = nf * 8 + 2 * t;
        Cb[(size_t)g * DD + c]           = __uint_as_float(f2tf(oacc[nf][0] * inv0));
        Cb[(size_t)g * DD + c + 1]       = __uint_as_float(f2tf(oacc[nf][1] * inv0));
        Cb[(size_t)(g + 8) * DD + c]     = __uint_as_float(f2tf(oacc[nf][2] * inv1));
        Cb[(size_t)(g + 8) * DD + c + 1] = __uint_as_float(f2tf(oacc[nf][3] * inv1));
    }
}

// ---------------------------------------------------------------------------
// Launch: 5 separate kernels.
// ---------------------------------------------------------------------------
extern "C" void kernel_launch(void* const* d_in, const int* in_sizes, int n_in,
                              void* d_out, int out_size) {
    const float* query = (const float*)d_in[0];
    const float* key_  = (const float*)d_in[1];
    const float* value = (const float*)d_in[2];
    const float* Wq = (const float*)d_in[3];
    const float* bq = (const float*)d_in[4];
    const float* Wk = (const float*)d_in[5];
    const float* bk = (const float*)d_in[6];
    const float* Wv = (const float*)d_in[7];
    const float* bv = (const float*)d_in[8];
    const float* Wo = (const float*)d_in[9];
    const float* bo = (const float*)d_in[10];
    float* out = (float*)d_out;

    float *pQ, *pK, *pV, *pC;
    cudaGetSymbolAddress((void**)&pQ, gQ);
    cudaGetSymbolAddress((void**)&pK, gK);
    cudaGetSymbolAddress((void**)&pV, gV);
    cudaGetSymbolAddress((void**)&pC, gC);

    cudaFuncSetAttribute(attn_kernel, cudaFuncAttributeMaxDynamicSharedMemorySize, ATTN_SMEM);

    dim3 ggrid(GN / 128, GM / 128);   // (8, 64)
    gemm_bias<<<ggrid, 128>>>(query, Wq, bq, pQ, 1);
    gemm_bias<<<ggrid, 128>>>(key_,  Wk, bk, pK, 1);
    gemm_bias<<<ggrid, 128>>>(value, Wv, bv, pV, 1);

    attn_kernel<<<dim3(SS / 64, HH, BB), 128, ATTN_SMEM>>>(pQ, pK, pV, pC);

    gemm_bias<<<ggrid, 128>>>(pC, Wo, bo, out, 0);
}

// round 14
// speedup vs baseline: 1.3579x; 1.1278x over previous
#include <cuda_runtime.h>
#include <cuda_fp16.h>
#include <cstdint>

#define BB   4
#define SS   2048
#define DD   1024
#define HH   16
#define DKK  64
#define GM   (BB*SS)
#define GK   DD
#define GN   DD

// ---------------------------------------------------------------------------
// Scratch (device globals; allocation-free per harness rules)
// ---------------------------------------------------------------------------
__device__ float gQ[BB*SS*DD];
__device__ float gK[BB*SS*DD];
__device__ float gV[BB*SS*DD];
__device__ float gC[BB*SS*DD];

// ---------------------------------------------------------------------------
// Helpers
// ---------------------------------------------------------------------------
__device__ __forceinline__ unsigned f2tf(float f) {
    unsigned r;
    asm("cvt.rna.tf32.f32 %0, %1;" : "=r"(r) : "f"(f));
    return r;
}
__device__ __forceinline__ float ex2(float x) {
    float r;
    asm("ex2.approx.ftz.f32 %0, %1;" : "=f"(r) : "f"(x));
    return r;
}
__device__ __forceinline__ unsigned packh2(float lo, float hi) {
    __half2 h = __floats2half2_rn(lo, hi);   // .x (low 16 bits) = lo
    return *(unsigned*)&h;
}
__device__ __forceinline__ void mma_tf32(float& d0, float& d1, float& d2, float& d3,
                                         unsigned a0, unsigned a1, unsigned a2, unsigned a3,
                                         unsigned b0, unsigned b1) {
    asm("mma.sync.aligned.m16n8k8.row.col.f32.tf32.tf32.f32 "
        "{%0,%1,%2,%3},{%4,%5,%6,%7},{%8,%9},{%0,%1,%2,%3};"
        : "+f"(d0), "+f"(d1), "+f"(d2), "+f"(d3)
        : "r"(a0), "r"(a1), "r"(a2), "r"(a3), "r"(b0), "r"(b1));
}
__device__ __forceinline__ void mma_f16(float& d0, float& d1, float& d2, float& d3,
                                        unsigned a0, unsigned a1, unsigned a2, unsigned a3,
                                        unsigned b0, unsigned b1) {
    asm("mma.sync.aligned.m16n8k16.row.col.f32.f16.f16.f32 "
        "{%0,%1,%2,%3},{%4,%5,%6,%7},{%8,%9},{%0,%1,%2,%3};"
        : "+f"(d0), "+f"(d1), "+f"(d2), "+f"(d3)
        : "r"(a0), "r"(a1), "r"(a2), "r"(a3), "r"(b0), "r"(b1));
}

// ---------------------------------------------------------------------------
// GEMM v3 (PROVEN ~135us, byte-exact): tf32 m16n8k8.
// CTA 128x128x32, 128 thr / 4 warps (2m x 2n), warp tile 64x64.
// ---------------------------------------------------------------------------
#define ASTR 36
#define BSTR 132

__global__ __launch_bounds__(128)
void gemm_bias(const float* __restrict__ X, const float* __restrict__ W,
               const float* __restrict__ bias, float* __restrict__ C, int round_out) {
    __shared__ unsigned As[128 * ASTR];
    __shared__ unsigned Bs[32 * BSTR];

    const int tid  = threadIdx.x;
    const int wid  = tid >> 5;
    const int lane = tid & 31;
    const int g    = lane >> 2;
    const int t    = lane & 3;
    const int wm   = wid & 1;
    const int wn   = wid >> 1;
    const int m0   = blockIdx.y * 128;
    const int n0   = blockIdx.x * 128;

    float acc[4][8][4];
#pragma unroll
    for (int mf = 0; mf < 4; mf++)
#pragma unroll
        for (int nf = 0; nf < 8; nf++)
#pragma unroll
            for (int r = 0; r < 4; r++) acc[mf][nf][r] = 0.f;

    for (int kt = 0; kt < GK / 32; kt++) {
        __syncthreads();
#pragma unroll
        for (int i = 0; i < 8; i++) {
            int idx = tid + i * 128;
            int r = idx >> 3, c4 = idx & 7;
            float4 v = *(const float4*)(X + (size_t)(m0 + r) * GK + kt * 32 + c4 * 4);
            unsigned* dst = &As[r * ASTR + c4 * 4];
            dst[0] = f2tf(v.x); dst[1] = f2tf(v.y); dst[2] = f2tf(v.z); dst[3] = f2tf(v.w);
        }
#pragma unroll
        for (int i = 0; i < 8; i++) {
            int idx = tid + i * 128;
            int r = idx >> 5, c4 = idx & 31;
            float4 v = *(const float4*)(W + (size_t)(kt * 32 + r) * GN + n0 + c4 * 4);
            unsigned* dst = &Bs[r * BSTR + c4 * 4];
            dst[0] = f2tf(v.x); dst[1] = f2tf(v.y); dst[2] = f2tf(v.z); dst[3] = f2tf(v.w);
        }
        __syncthreads();

#pragma unroll
        for (int ks = 0; ks < 4; ks++) {
            unsigned a[4][4];
#pragma unroll
            for (int mf = 0; mf < 4; mf++) {
                int rb = wm * 64 + mf * 16;
                a[mf][0] = As[(rb + g)     * ASTR + ks * 8 + t];
                a[mf][1] = As[(rb + g + 8) * ASTR + ks * 8 + t];
                a[mf][2] = As[(rb + g)     * ASTR + ks * 8 + t + 4];
                a[mf][3] = As[(rb + g + 8) * ASTR + ks * 8 + t + 4];
            }
#pragma unroll
            for (int nf = 0; nf < 8; nf++) {
                unsigned b0 = Bs[(ks * 8 + t)     * BSTR + wn * 64 + nf * 8 + g];
                unsigned b1 = Bs[(ks * 8 + t + 4) * BSTR + wn * 64 + nf * 8 + g];
#pragma unroll
                for (int mf = 0; mf < 4; mf++)
                    mma_tf32(acc[mf][nf][0], acc[mf][nf][1], acc[mf][nf][2], acc[mf][nf][3],
                             a[mf][0], a[mf][1], a[mf][2], a[mf][3], b0, b1);
            }
        }
    }

#pragma unroll
    for (int mf = 0; mf < 4; mf++) {
#pragma unroll
        for (int nf = 0; nf < 8; nf++) {
            int row = m0 + wm * 64 + mf * 16 + g;
            int col = n0 + wn * 64 + nf * 8 + 2 * t;
            float bv0 = bias[col], bv1 = bias[col + 1];
            float v00 = acc[mf][nf][0] + bv0;
            float v01 = acc[mf][nf][1] + bv1;
            float v10 = acc[mf][nf][2] + bv0;
            float v11 = acc[mf][nf][3] + bv1;
            if (round_out) {
                v00 = __uint_as_float(f2tf(v00));
                v01 = __uint_as_float(f2tf(v01));
                v10 = __uint_as_float(f2tf(v10));
                v11 = __uint_as_float(f2tf(v11));
            }
            C[(size_t)row * GN + col]           = v00;
            C[(size_t)row * GN + col + 1]       = v01;
            C[(size_t)(row + 8) * GN + col]     = v10;
            C[(size_t)(row + 8) * GN + col + 1] = v11;
        }
    }
}

// ---------------------------------------------------------------------------
// Flash attention v8: round-10 v6 (256 thr, q-tile 128, PROVEN 474.6us) with
// ONE delta: next tile's K held in registers (8x uint4), LDGs issued right
// after the staging sync so their latency overlaps the full compute phase.
// ---------------------------------------------------------------------------
#define KST 68
#define VST2 72
#define VOFF (128*KST)
#define ATTN_SMEM ((128*KST + 64*VST2) * 4)   // 53248 bytes

__global__ __launch_bounds__(256)
void attn_kernel(const float* __restrict__ gq, const float* __restrict__ gk,
                 const float* __restrict__ gv, float* __restrict__ gc) {
    extern __shared__ unsigned sm[];
    unsigned* Ks = sm;              // k-permuted tf32 [128][KST]
    unsigned* Vp = sm + VOFF;       // half2 row-pairs [64][VST2]

    const int b  = blockIdx.z;
    const int h  = blockIdx.y;
    const int q0 = blockIdx.x * 128;
    const int tid  = threadIdx.x;
    const int wid  = tid >> 5;
    const int lane = tid & 31;
    const int g    = lane >> 2;
    const int t    = lane & 3;
    const float L2E = 1.44269504f;

    unsigned qf[8][4];
    {
        const float* Qb = gq + ((size_t)(b * SS + q0 + wid * 16)) * DD + h * DKK;
#pragma unroll
        for (int ks = 0; ks < 8; ks++) {
            qf[ks][0] = __float_as_uint(Qb[(size_t)g * DD + ks * 8 + t] * 0.125f);
            qf[ks][1] = __float_as_uint(Qb[(size_t)(g + 8) * DD + ks * 8 + t] * 0.125f);
            qf[ks][2] = __float_as_uint(Qb[(size_t)g * DD + ks * 8 + t + 4] * 0.125f);
            qf[ks][3] = __float_as_uint(Qb[(size_t)(g + 8) * DD + ks * 8 + t + 4] * 0.125f);
        }
    }

    float mr0 = -1e30f, mr1 = -1e30f, l0 = 0.f, l1 = 0.f;
    float oacc[8][4];
#pragma unroll
    for (int nf = 0; nf < 8; nf++)
#pragma unroll
        for (int r = 0; r < 4; r++) oacc[nf][r] = 0.f;

    const uint4* Kb = (const uint4*)(gk + (size_t)b * SS * DD + h * DKK);
    const float* Vb = gv + (size_t)b * SS * DD + h * DKK;
    const int RSTR4 = DD / 4;
    const int sr = tid >> 4, sc4 = tid & 15;   // K staging (row, chunk) base
    const int NT = SS / 128;

    // Prologue: prefetch K tile 0 into registers
    uint4 kr[8];
#pragma unroll
    for (int i = 0; i < 8; i++)
        kr[i] = Kb[(size_t)(sr + i * 16) * RSTR4 + sc4];

    for (int kt = 0; kt < NT; kt++) {
        __syncthreads();
        // K staging: STS-only from prefetched registers (permuted layout)
#pragma unroll
        for (int i = 0; i < 8; i++) {
            int r = sr + i * 16, c = sc4 * 4;
            int kbase = r * KST;
            Ks[kbase + ((c + 0) & 7) * 8 + ((c + 0) >> 3)] = kr[i].x;
            Ks[kbase + ((c + 1) & 7) * 8 + ((c + 1) >> 3)] = kr[i].y;
            Ks[kbase + ((c + 2) & 7) * 8 + ((c + 2) >> 3)] = kr[i].z;
            Ks[kbase + ((c + 3) & 7) * 8 + ((c + 3) >> 3)] = kr[i].w;
        }
        // V staging (unchanged): LDG + fp16 pack + STS
#pragma unroll
        for (int i = 0; i < 4; i++) {
            int idx = tid + i * 256;
            int rp = idx >> 4, c4 = idx & 15;
            const float* g0 = Vb + (size_t)(kt * 128 + 2 * rp) * DD + c4 * 4;
            float4 va = *(const float4*)g0;
            float4 vb2 = *(const float4*)(g0 + DD);
            uint4 o;
            o.x = packh2(va.x, vb2.x);
            o.y = packh2(va.y, vb2.y);
            o.z = packh2(va.z, vb2.z);
            o.w = packh2(va.w, vb2.w);
            *(uint4*)&Vp[rp * VST2 + c4 * 4] = o;
        }
        __syncthreads();

        // Prefetch NEXT K tile: LDG latency overlaps the whole compute phase
        if (kt + 1 < NT) {
#pragma unroll
            for (int i = 0; i < 8; i++)
                kr[i] = Kb[(size_t)((kt + 1) * 128 + sr + i * 16) * RSTR4 + sc4];
        }

        // S = Q K^T : 16 x 128 per warp (tf32)
        float sacc[16][4];
#pragma unroll
        for (int nf = 0; nf < 16; nf++)
#pragma unroll
            for (int r = 0; r < 4; r++) sacc[nf][r] = 0.f;

#pragma unroll
        for (int nf = 0; nf < 16; nf++) {
            const uint4* kp = (const uint4*)&Ks[(nf * 8 + g) * KST + t * 8];
            uint4 k0 = kp[0], k1 = kp[1];
            const uint4* kq = (const uint4*)&Ks[(nf * 8 + g) * KST + (t + 4) * 8];
            uint4 k2 = kq[0], k3 = kq[1];
            mma_tf32(sacc[nf][0], sacc[nf][1], sacc[nf][2], sacc[nf][3],
                     qf[0][0], qf[0][1], qf[0][2], qf[0][3], k0.x, k2.x);
            mma_tf32(sacc[nf][0], sacc[nf][1], sacc[nf][2], sacc[nf][3],
                     qf[1][0], qf[1][1], qf[1][2], qf[1][3], k0.y, k2.y);
            mma_tf32(sacc[nf][0], sacc[nf][1], sacc[nf][2], sacc[nf][3],
                     qf[2][0], qf[2][1], qf[2][2], qf[2][3], k0.z, k2.z);
            mma_tf32(sacc[nf][0], sacc[nf][1], sacc[nf][2], sacc[nf][3],
                     qf[3][0], qf[3][1], qf[3][2], qf[3][3], k0.w, k2.w);
            mma_tf32(sacc[nf][0], sacc[nf][1], sacc[nf][2], sacc[nf][3],
                     qf[4][0], qf[4][1], qf[4][2], qf[4][3], k1.x, k3.x);
            mma_tf32(sacc[nf][0], sacc[nf][1], sacc[nf][2], sacc[nf][3],
                     qf[5][0], qf[5][1], qf[5][2], qf[5][3], k1.y, k3.y);
            mma_tf32(sacc[nf][0], sacc[nf][1], sacc[nf][2], sacc[nf][3],
                     qf[6][0], qf[6][1], qf[6][2], qf[6][3], k1.z, k3.z);
            mma_tf32(sacc[nf][0], sacc[nf][1], sacc[nf][2], sacc[nf][3],
                     qf[7][0], qf[7][1], qf[7][2], qf[7][3], k1.w, k3.w);
        }

        // online softmax
        float rmax0 = -1e30f, rmax1 = -1e30f;
#pragma unroll
        for (int nf = 0; nf < 16; nf++) {
            rmax0 = fmaxf(rmax0, fmaxf(sacc[nf][0], sacc[nf][1]));
            rmax1 = fmaxf(rmax1, fmaxf(sacc[nf][2], sacc[nf][3]));
        }
        rmax0 = fmaxf(rmax0, __shfl_xor_sync(0xffffffffu, rmax0, 1));
        rmax0 = fmaxf(rmax0, __shfl_xor_sync(0xffffffffu, rmax0, 2));
        rmax1 = fmaxf(rmax1, __shfl_xor_sync(0xffffffffu, rmax1, 1));
        rmax1 = fmaxf(rmax1, __shfl_xor_sync(0xffffffffu, rmax1, 2));
        float mn0 = fmaxf(mr0, rmax0), mn1 = fmaxf(mr1, rmax1);
        float alpha0 = ex2((mr0 - mn0) * L2E);
        float alpha1 = ex2((mr1 - mn1) * L2E);
        mr0 = mn0; mr1 = mn1;

        // exp + fp16 pack (accumulator layout == fp16 A-fragment layout)
        unsigned pah[16][2];
        float rs0 = 0.f, rs1 = 0.f;
#pragma unroll
        for (int nf = 0; nf < 16; nf++) {
            float p0 = ex2((sacc[nf][0] - mn0) * L2E);
            float p1 = ex2((sacc[nf][1] - mn0) * L2E);
            float p2 = ex2((sacc[nf][2] - mn1) * L2E);
            float p3 = ex2((sacc[nf][3] - mn1) * L2E);
            rs0 += p0 + p1;
            rs1 += p2 + p3;
            pah[nf][0] = packh2(p0, p1);
            pah[nf][1] = packh2(p2, p3);
        }
        rs0 += __shfl_xor_sync(0xffffffffu, rs0, 1);
        rs0 += __shfl_xor_sync(0xffffffffu, rs0, 2);
        rs1 += __shfl_xor_sync(0xffffffffu, rs1, 1);
        rs1 += __shfl_xor_sync(0xffffffffu, rs1, 2);
        l0 = l0 * alpha0 + rs0;
        l1 = l1 * alpha1 + rs1;
#pragma unroll
        for (int nf = 0; nf < 8; nf++) {
            oacc[nf][0] *= alpha0; oacc[nf][1] *= alpha0;
            oacc[nf][2] *= alpha1; oacc[nf][3] *= alpha1;
        }

        // O += P V : fp16 m16n8k16
#pragma unroll
        for (int nf = 0; nf < 8; nf++) {
#pragma unroll
            for (int kp = 0; kp < 8; kp++) {
                unsigned b0 = Vp[(kp * 8 + t)     * VST2 + nf * 8 + g];
                unsigned b1 = Vp[(kp * 8 + t + 4) * VST2 + nf * 8 + g];
                mma_f16(oacc[nf][0], oacc[nf][1], oacc[nf][2], oacc[nf][3],
                        pah[2 * kp][0], pah[2 * kp][1],
                        pah[2 * kp + 1][0], pah[2 * kp + 1][1], b0, b1);
            }
        }
    }

    // epilogue: normalize + round (ctx feeds the tf32 O-projection)
    float inv0 = 1.f / l0, inv1 = 1.f / l1;
    float* Cb = gc + ((size_t)(b * SS + q0 + wid * 16)) * DD + h * DKK;
#pragma unroll
    for (int nf = 0; nf < 8; nf++) {
        int c = nf * 8 + 2 * t;
        Cb[(size_t)g * DD + c]           = __uint_as_float(f2tf(oacc[nf][0] * inv0));
        Cb[(size_t)g * DD + c + 1]       = __uint_as_float(f2tf(oacc[nf][1] * inv0));
        Cb[(size_t)(g + 8) * DD + c]     = __uint_as_float(f2tf(oacc[nf][2] * inv1));
        Cb[(size_t)(g + 8) * DD + c + 1] = __uint_as_float(f2tf(oacc[nf][3] * inv1));
    }
}

// ---------------------------------------------------------------------------
// Launch: 5 separate kernels.
// ---------------------------------------------------------------------------
extern "C" void kernel_launch(void* const* d_in, const int* in_sizes, int n_in,
                              void* d_out, int out_size) {
    const float* query = (const float*)d_in[0];
    const float* key_  = (const float*)d_in[1];
    const float* value = (const float*)d_in[2];
    const float* Wq = (const float*)d_in[3];
    const float* bq = (const float*)d_in[4];
    const float* Wk = (const float*)d_in[5];
    const float* bk = (const float*)d_in[6];
    const float* Wv = (const float*)d_in[7];
    const float* bv = (const float*)d_in[8];
    const float* Wo = (const float*)d_in[9];
    const float* bo = (const float*)d_in[10];
    float* out = (float*)d_out;

    float *pQ, *pK, *pV, *pC;
    cudaGetSymbolAddress((void**)&pQ, gQ);
    cudaGetSymbolAddress((void**)&pK, gK);
    cudaGetSymbolAddress((void**)&pV, gV);
    cudaGetSymbolAddress((void**)&pC, gC);

    cudaFuncSetAttribute(attn_kernel, cudaFuncAttributeMaxDynamicSharedMemorySize, ATTN_SMEM);

    dim3 ggrid(GN / 128, GM / 128);   // (8, 64)
    gemm_bias<<<ggrid, 128>>>(query, Wq, bq, pQ, 1);
    gemm_bias<<<ggrid, 128>>>(key_,  Wk, bk, pK, 1);
    gemm_bias<<<ggrid, 128>>>(value, Wv, bv, pV, 1);

    attn_kernel<<<dim3(SS / 128, HH, BB), 256, ATTN_SMEM>>>(pQ, pK, pV, pC);

    gemm_bias<<<ggrid, 128>>>(pC, Wo, bo, out, 0);
}